// round 10
// baseline (speedup 1.0000x reference)
#include <cuda_runtime.h>
#include <math.h>

#define Tlen 1024
#define Fdim 304
#define Hdim 304
#define G3   912
#define Dvoc 128
#define NCTA 76

#define LOG_N   (64*127*128)
#define TGT_OFF LOG_N
#define ASR_OFF (LOG_N + 64*127)
#define FULL_N  (ASR_OFF + 64*127)

__device__ float    g_XW[(size_t)64 * Tlen * G3];   // [b*1024+t][912]
__device__ float    g_DW[Dvoc * G3];
__device__ float    g_h[2][64 * Hdim];              // ping-pong: [buf][b*304+k]
__device__ int      g_tok[64];
__device__ unsigned g_barE, g_barD;

__device__ __forceinline__ unsigned long long pk(float lo, float hi) {
    unsigned long long v;
    asm("mov.b64 %0, {%1, %2};" : "=l"(v) : "f"(lo), "f"(hi));
    return v;
}
__device__ __forceinline__ float2 unpk(unsigned long long v) {
    float2 r;
    asm("mov.b64 {%0, %1}, %2;" : "=f"(r.x), "=f"(r.y) : "l"(v));
    return r;
}
__device__ __forceinline__ unsigned long long ffma2(unsigned long long a,
                                                    unsigned long long b,
                                                    unsigned long long c) {
    unsigned long long d;
    asm("fma.rn.f32x2 %0, %1, %2, %3;" : "=l"(d) : "l"(a), "l"(b), "l"(c));
    return d;
}
__device__ __forceinline__ float sigm(float x) { return 1.0f / (1.0f + expf(-x)); }

__device__ __forceinline__ void gbar(unsigned* cnt, unsigned tgt) {
    __threadfence();
    __syncthreads();
    if (threadIdx.x == 0) {
        atomicAdd(cnt, 1u);
        while (*((volatile unsigned*)cnt) < tgt) {}
    }
    __syncthreads();
}

// ---- init: barriers, tokens, target_cal, zero h buf0 ----
__global__ void init_kernel(const int* __restrict__ target, float* __restrict__ out, int full) {
    const int b = blockIdx.x, j = threadIdx.x;
    if (b == 0 && j == 0) { g_barE = 0u; g_barD = 0u; }
    if (j == 0) g_tok[b] = target[b * 128] & 127;
    for (int k = j; k < Hdim; k += 128) g_h[0][b * Hdim + k] = 0.0f;
    if (full)
        for (int i = j; i < 127; i += 128)
            out[TGT_OFF + b * 127 + i] = (float)target[b * 128 + i + 1];
}

// ---- DW = emb @ dec_Wih^T + dec_bih ----
__global__ void __launch_bounds__(928)
dw_kernel(const float* __restrict__ emb, const float* __restrict__ Wih,
          const float* __restrict__ bih) {
    __shared__ __align__(16) float e_s[Fdim];
    const int d = blockIdx.x, j = threadIdx.x;
    if (j < Fdim) e_s[j] = emb[(size_t)d * Fdim + j];
    __syncthreads();
    if (j >= G3) return;
    const float4* w4 = (const float4*)(Wih + (size_t)j * Fdim);
    const float4* e4 = (const float4*)e_s;
    float acc = 0.0f;
#pragma unroll 4
    for (int i = 0; i < Fdim / 4; i++) {
        float4 wv = w4[i], ev = e4[i];
        acc += ev.x * wv.x + ev.y * wv.y + ev.z * wv.z + ev.w * wv.w;
    }
    g_DW[d * G3 + j] = acc + bih[j];
}

// ---- GEMM: g_XW = x @ enc_Wih^T + bih  (M=65536, N=912 pad 1024, K=304) ----
__global__ void __launch_bounds__(256)
gemm_xw(const float* __restrict__ X, const float* __restrict__ W,
        const float* __restrict__ bias) {
    __shared__ __align__(16) float As[16][132];
    __shared__ __align__(16) float Bs[16][132];
    const int    n0 = blockIdx.x * 128;
    const size_t m0 = (size_t)blockIdx.y * 128;
    const int t = threadIdx.x;
    const int tx = t & 15, ty = t >> 4;
    const int lr = t >> 2, lc = (t & 3) * 4;

    unsigned long long acc[8][4];
#pragma unroll
    for (int i = 0; i < 8; i++)
#pragma unroll
        for (int j = 0; j < 4; j++) acc[i][j] = 0ull;

    const float* Xb = X + m0 * Fdim;
    const float4 z4 = make_float4(0.f, 0.f, 0.f, 0.f);

    for (int k0 = 0; k0 < Fdim; k0 += 16) {
        float4 av0 = *(const float4*)(Xb + (size_t)lr        * Fdim + k0 + lc);
        float4 av1 = *(const float4*)(Xb + (size_t)(lr + 64) * Fdim + k0 + lc);
        int nr0 = n0 + lr, nr1 = n0 + lr + 64;
        float4 bv0 = (nr0 < G3) ? *(const float4*)(W + (size_t)nr0 * Fdim + k0 + lc) : z4;
        float4 bv1 = (nr1 < G3) ? *(const float4*)(W + (size_t)nr1 * Fdim + k0 + lc) : z4;
        __syncthreads();
        As[lc+0][lr] = av0.x; As[lc+1][lr] = av0.y; As[lc+2][lr] = av0.z; As[lc+3][lr] = av0.w;
        As[lc+0][lr+64] = av1.x; As[lc+1][lr+64] = av1.y; As[lc+2][lr+64] = av1.z; As[lc+3][lr+64] = av1.w;
        Bs[lc+0][lr] = bv0.x; Bs[lc+1][lr] = bv0.y; Bs[lc+2][lr] = bv0.z; Bs[lc+3][lr] = bv0.w;
        Bs[lc+0][lr+64] = bv1.x; Bs[lc+1][lr+64] = bv1.y; Bs[lc+2][lr+64] = bv1.z; Bs[lc+3][lr+64] = bv1.w;
        __syncthreads();
#pragma unroll
        for (int kk = 0; kk < 16; kk++) {
            float4 a0 = *(const float4*)&As[kk][ty * 8];
            float4 a1 = *(const float4*)&As[kk][ty * 8 + 4];
            ulonglong2 b01 = *(const ulonglong2*)&Bs[kk][tx * 8];
            ulonglong2 b23 = *(const ulonglong2*)&Bs[kk][tx * 8 + 4];
            unsigned long long bb[4] = {b01.x, b01.y, b23.x, b23.y};
            float a[8] = {a0.x, a0.y, a0.z, a0.w, a1.x, a1.y, a1.z, a1.w};
#pragma unroll
            for (int i = 0; i < 8; i++) {
                unsigned long long ad = pk(a[i], a[i]);
#pragma unroll
                for (int jj = 0; jj < 4; jj++) acc[i][jj] = ffma2(ad, bb[jj], acc[i][jj]);
            }
        }
    }
#pragma unroll
    for (int i = 0; i < 8; i++) {
        size_t m = m0 + (size_t)ty * 8 + i;
        float* Crow = g_XW + m * G3;
#pragma unroll
        for (int jj = 0; jj < 4; jj++) {
            int n = n0 + tx * 8 + jj * 2;
            if (n < G3) {
                float2 v = unpk(acc[i][jj]);
                float2 o; o.x = v.x + bias[n]; o.y = v.y + bias[n + 1];
                *(float2*)(Crow + n) = o;
            }
        }
    }
}

// ---- shared recurrent step pieces ----
// smem: wd[12*304] (f32x2-dup, 8B each) | ps[12*8*64] floats | extras
__device__ __forceinline__ void stage_w(unsigned long long* wd, const float* Whh,
                                        int c, int tid) {
    for (int i = tid; i < 12 * Hdim; i += 256) {
        int lr = i / Hdim, k = i - lr * Hdim;
        int gr = (lr >> 2) * Hdim + 4 * c + (lr & 3);
        float w = Whh[(size_t)gr * Hdim + k];
        wd[i] = pk(w, w);
    }
}

// matvec: thread (k8 = tid>>5, bp = tid&31) handles batches 2bp,2bp+1, k in [k8*38, k8*38+38)
__device__ __forceinline__ void gate_matvec(const unsigned long long* wd, float* ps,
                                            const float* hb, int tid) {
    const int k8 = tid >> 5, bp = tid & 31, b0 = 2 * bp;
    unsigned long long acc[12];
#pragma unroll
    for (int r = 0; r < 12; r++) acc[r] = 0ull;
    const float2* h0 = (const float2*)(hb + (size_t)b0 * Hdim + k8 * 38);
    const float2* h1 = (const float2*)(hb + (size_t)(b0 + 1) * Hdim + k8 * 38);
    const unsigned long long* wbase = wd + k8 * 38;
#pragma unroll
    for (int kk = 0; kk < 19; kk++) {
        float2 ha = __ldcg(h0 + kk), hc = __ldcg(h1 + kk);
        unsigned long long a0 = pk(ha.x, hc.x), a1 = pk(ha.y, hc.y);
#pragma unroll
        for (int r = 0; r < 12; r++) {
            ulonglong2 wv = *(const ulonglong2*)(wbase + r * Hdim + 2 * kk);
            acc[r] = ffma2(a0, wv.x, acc[r]);
            acc[r] = ffma2(a1, wv.y, acc[r]);
        }
    }
#pragma unroll
    for (int r = 0; r < 12; r++) {
        float2 v = unpk(acc[r]);
        *(float2*)&ps[(r * 8 + k8) * 64 + b0] = v;
    }
}

// update: thread (ci = tid>>6, b = tid&63) finishes component 4c+ci for batch b
__device__ __forceinline__ float gru_update(const float* ps, int ci, int b,
                                            float giR, float giZ, float giN,
                                            float bR, float bZ, float bN, float hold) {
    float ghr = 0.f, ghz = 0.f, ghn = 0.f;
#pragma unroll
    for (int k = 0; k < 8; k++) {
        ghr += ps[((0 + ci) * 8 + k) * 64 + b];
        ghz += ps[((4 + ci) * 8 + k) * 64 + b];
        ghn += ps[((8 + ci) * 8 + k) * 64 + b];
    }
    float r = sigm(giR + ghr + bR);
    float z = sigm(giZ + ghz + bZ);
    float n = tanhf(giN + r * (ghn + bN));
    return (1.f - z) * n + z * hold;
}

// ---- encoder: 76 persistent CTAs, 1 grid barrier per step ----
__global__ void __launch_bounds__(256, 1)
enc_kernel(const float* __restrict__ Whh, const float* __restrict__ bhh) {
    extern __shared__ float sm[];
    unsigned long long* wd = (unsigned long long*)sm;   // 3648 entries
    float* ps = sm + 7296;                              // 6144 floats
    const int c = blockIdx.x, tid = threadIdx.x;
    const int ci = tid >> 6, b = tid & 63;

    stage_w(wd, Whh, c, tid);
    const float bR = bhh[4 * c + ci], bZ = bhh[Hdim + 4 * c + ci], bN = bhh[2 * Hdim + 4 * c + ci];
    unsigned ph = 1;
    gbar(&g_barE, ph * NCTA);   // h buf0 zeroed by init (prior launch), weights staged

    for (int t = 0; t < Tlen; t++) {
        const float* gx = g_XW + ((size_t)b * Tlen + t) * G3 + 4 * c + ci;
        float giR = __ldg(gx), giZ = __ldg(gx + Hdim), giN = __ldg(gx + 2 * Hdim);
        const float* hb = g_h[t & 1];
        gate_matvec(wd, ps, hb, tid);
        __syncthreads();
        float hold = __ldcg(&hb[(size_t)b * Hdim + 4 * c + ci]);
        g_h[(t + 1) & 1][(size_t)b * Hdim + 4 * c + ci] =
            gru_update(ps, ci, b, giR, giZ, giN, bR, bZ, bN, hold);
        ph++;
        gbar(&g_barE, ph * NCTA);
    }
}

// ---- decoder: 76 persistent CTAs, 3 barriers per step ----
__global__ void __launch_bounds__(256, 1)
dec_kernel(const float* __restrict__ Whh, const float* __restrict__ bhh,
           const float* __restrict__ linW, const float* __restrict__ linb,
           float* __restrict__ out, int full) {
    extern __shared__ float sm[];
    unsigned long long* wd = (unsigned long long*)sm;   // 3648
    float* ps  = sm + 7296;                             // 6144
    float* lw  = ps + 6144;                             // 608
    float* red = lw + 608;                              // 256
    __shared__ float rv[4];
    __shared__ int   ri[4];
    const int c = blockIdx.x, tid = threadIdx.x;
    const int ci = tid >> 6, b = tid & 63;

    stage_w(wd, Whh, c, tid);
    const float bR = bhh[4 * c + ci], bZ = bhh[Hdim + 4 * c + ci], bN = bhh[2 * Hdim + 4 * c + ci];
    float lb = 0.f;
    if (c < 64) {
        for (int i = tid; i < 2 * Hdim; i += 256)
            lw[i] = linW[(size_t)(2 * c + (i >= Hdim)) * Hdim + (i >= Hdim ? i - Hdim : i)];
        lb = linb[2 * c + ((tid >> 6) & 1)];
    }
    unsigned ph = 0;

    for (int l = 0; l < 127; l++) {
        const int rb = l & 1, wb = rb ^ 1;
        // phase 1: GRU step
        int tok = *((volatile int*)&g_tok[b]);
        const float* gx = g_DW + (size_t)tok * G3 + 4 * c + ci;
        float giR = __ldg(gx), giZ = __ldg(gx + Hdim), giN = __ldg(gx + 2 * Hdim);
        const float* hb = g_h[rb];
        gate_matvec(wd, ps, hb, tid);
        __syncthreads();
        float hold = __ldcg(&hb[(size_t)b * Hdim + 4 * c + ci]);
        g_h[wb][(size_t)b * Hdim + 4 * c + ci] =
            gru_update(ps, ci, b, giR, giZ, giN, bR, bZ, bN, hold);
        gbar(&g_barD, (++ph) * NCTA);

        // phase 2: logits (CTAs 0..63 compute d = 2c, 2c+1 for all batches)
        float lacc = 0.f;
        if (c < 64) {
            const int bb = tid & 63, d2 = (tid >> 6) & 1, kh = tid >> 7;
            const float2* hrow = (const float2*)(g_h[wb] + (size_t)bb * Hdim + kh * 152);
            const float2* wrow = (const float2*)(lw + d2 * Hdim + kh * 152);
#pragma unroll 4
            for (int i = 0; i < 76; i++) {
                float2 hv = __ldcg(hrow + i);
                float2 wv = wrow[i];
                lacc += hv.x * wv.x + hv.y * wv.y;
            }
        }
        red[tid] = lacc;
        __syncthreads();
        if (c < 64 && tid < 128) {
            const int bb = tid & 63, d2 = (tid >> 6) & 1;
            float v = red[tid] + red[tid + 128] + lb;
            out[((size_t)bb * 127 + l) * Dvoc + 2 * c + d2] = v;
        }
        gbar(&g_barD, (++ph) * NCTA);

        // phase 3: argmax per batch (CTA c = batch c)
        if (c < 64 && tid < 128) {
            float v = __ldcg(&out[((size_t)c * 127 + l) * Dvoc + tid]);
            int   idx = tid;
#pragma unroll
            for (int o = 16; o > 0; o >>= 1) {
                float ov = __shfl_down_sync(0xffffffffu, v, o);
                int   oi = __shfl_down_sync(0xffffffffu, idx, o);
                if (ov > v || (ov == v && oi < idx)) { v = ov; idx = oi; }
            }
            if ((tid & 31) == 0) { rv[tid >> 5] = v; ri[tid >> 5] = idx; }
        }
        __syncthreads();
        if (c < 64 && tid == 0) {
            float bv = rv[0]; int bi = ri[0];
#pragma unroll
            for (int w = 1; w < 4; w++)
                if (rv[w] > bv || (rv[w] == bv && ri[w] < bi)) { bv = rv[w]; bi = ri[w]; }
            g_tok[c] = bi;
            if (full) out[ASR_OFF + c * 127 + l] = (float)bi;
        }
        gbar(&g_barD, (++ph) * NCTA);
    }
}

extern "C" void kernel_launch(void* const* d_in, const int* in_sizes, int n_in,
                              void* d_out, int out_size) {
    const float* x    = (const float*)d_in[0];
    const int*   tgt  = (const int*)  d_in[1];
    const float* emb  = (const float*)d_in[2];
    const float* eWih = (const float*)d_in[3];
    const float* eWhh = (const float*)d_in[4];
    const float* ebih = (const float*)d_in[5];
    const float* ebhh = (const float*)d_in[6];
    const float* dWih = (const float*)d_in[7];
    const float* dWhh = (const float*)d_in[8];
    const float* dbih = (const float*)d_in[9];
    const float* dbhh = (const float*)d_in[10];
    const float* linW = (const float*)d_in[11];
    const float* linb = (const float*)d_in[12];
    (void)in_sizes; (void)n_in;
    float* out = (float*)d_out;
    int full = (out_size >= FULL_N) ? 1 : 0;

    static int attr_done = 0;
    if (!attr_done) {
        cudaFuncSetAttribute(enc_kernel, cudaFuncAttributeMaxDynamicSharedMemorySize, 56 * 1024);
        cudaFuncSetAttribute(dec_kernel, cudaFuncAttributeMaxDynamicSharedMemorySize, 60 * 1024);
        attr_done = 1;
    }
    const int smE = (7296 + 6144) * 4;           // 53760 B
    const int smD = (7296 + 6144 + 608 + 256) * 4; // 57216 B

    init_kernel<<<64, 128>>>(tgt, out, full);
    dw_kernel<<<Dvoc, 928>>>(emb, dWih, dbih);
    gemm_xw<<<dim3(8, 512), 256>>>(x, eWih, ebih);
    enc_kernel<<<NCTA, 256, smE>>>(eWhh, ebhh);
    dec_kernel<<<NCTA, 256, smD>>>(dWhh, dbhh, linW, linb, out, full);
}

// round 12
// speedup vs baseline: 1.9015x; 1.9015x over previous
#include <cuda_runtime.h>
#include <math.h>

#define Tlen 1024
#define Fdim 304
#define Hdim 304
#define G3   912
#define Dvoc 128
#define NCTA 76

#define LOG_N   (64*127*128)
#define TGT_OFF LOG_N
#define ASR_OFF (LOG_N + 64*127)
#define FULL_N  (ASR_OFF + 64*127)

__device__ float    g_XW[(size_t)64 * Tlen * G3];   // [b*1024+t][912]
__device__ float    g_DW[Dvoc * G3];                // [tok][912]
__device__ float    g_h2[2][Hdim * 64];             // ping-pong h: [buf][k*64+b]
__device__ int      g_tok[64];
__device__ unsigned g_barE, g_barD;

__device__ __forceinline__ unsigned long long pk(float lo, float hi) {
    unsigned long long v;
    asm("mov.b64 %0, {%1, %2};" : "=l"(v) : "f"(lo), "f"(hi));
    return v;
}
__device__ __forceinline__ float2 unpk(unsigned long long v) {
    float2 r;
    asm("mov.b64 {%0, %1}, %2;" : "=f"(r.x), "=f"(r.y) : "l"(v));
    return r;
}
__device__ __forceinline__ unsigned long long ffma2(unsigned long long a,
                                                    unsigned long long b,
                                                    unsigned long long c) {
    unsigned long long d;
    asm("fma.rn.f32x2 %0, %1, %2, %3;" : "=l"(d) : "l"(a), "l"(b), "l"(c));
    return d;
}
__device__ __forceinline__ float sigm(float x) { return 1.0f / (1.0f + expf(-x)); }

__device__ __forceinline__ void gbar(unsigned* cnt, unsigned tgt) {
    __threadfence();
    __syncthreads();
    if (threadIdx.x == 0) {
        atomicAdd(cnt, 1u);
        while (*((volatile unsigned*)cnt) < tgt) {}
    }
    __syncthreads();
}

__global__ void init_kernel(const int* __restrict__ target, float* __restrict__ out, int full) {
    const int b = blockIdx.x, j = threadIdx.x;
    if (b == 0 && j == 0) { g_barE = 0u; g_barD = 0u; }
    if (j == 0) g_tok[b] = target[b * 128] & 127;
    for (int i = b * 128 + j; i < Hdim * 64; i += 64 * 128) g_h2[0][i] = 0.0f;
    if (full)
        for (int i = j; i < 127; i += 128)
            out[TGT_OFF + b * 127 + i] = (float)target[b * 128 + i + 1];
}

__global__ void __launch_bounds__(928)
dw_kernel(const float* __restrict__ emb, const float* __restrict__ Wih,
          const float* __restrict__ bih) {
    __shared__ __align__(16) float e_s[Fdim];
    const int d = blockIdx.x, j = threadIdx.x;
    if (j < Fdim) e_s[j] = emb[(size_t)d * Fdim + j];
    __syncthreads();
    if (j >= G3) return;
    const float4* w4 = (const float4*)(Wih + (size_t)j * Fdim);
    const float4* e4 = (const float4*)e_s;
    float acc = 0.0f;
#pragma unroll 4
    for (int i = 0; i < Fdim / 4; i++) {
        float4 wv = w4[i], ev = e4[i];
        acc = __fmaf_rn(ev.x, wv.x, acc);
        acc = __fmaf_rn(ev.y, wv.y, acc);
        acc = __fmaf_rn(ev.z, wv.z, acc);
        acc = __fmaf_rn(ev.w, wv.w, acc);
    }
    g_DW[d * G3 + j] = __fadd_rn(acc, bih[j]);
}

// ---- GEMM: g_XW = x @ enc_Wih^T + bih  (M=65536, N=912, K=304) ----
__global__ void __launch_bounds__(256)
gemm_xw(const float* __restrict__ X, const float* __restrict__ W,
        const float* __restrict__ bias) {
    __shared__ __align__(16) float As[16][132];
    __shared__ __align__(16) float Bs[16][132];
    const int    n0 = blockIdx.x * 128;
    const size_t m0 = (size_t)blockIdx.y * 128;
    const int t = threadIdx.x;
    const int tx = t & 15, ty = t >> 4;
    const int lr = t >> 2, lc = (t & 3) * 4;

    unsigned long long acc[8][4];
#pragma unroll
    for (int i = 0; i < 8; i++)
#pragma unroll
        for (int j = 0; j < 4; j++) acc[i][j] = 0ull;

    const float* Xb = X + m0 * Fdim;
    const float4 z4 = make_float4(0.f, 0.f, 0.f, 0.f);

    for (int k0 = 0; k0 < Fdim; k0 += 16) {
        float4 av0 = *(const float4*)(Xb + (size_t)lr        * Fdim + k0 + lc);
        float4 av1 = *(const float4*)(Xb + (size_t)(lr + 64) * Fdim + k0 + lc);
        int nr0 = n0 + lr, nr1 = n0 + lr + 64;
        float4 bv0 = (nr0 < G3) ? *(const float4*)(W + (size_t)nr0 * Fdim + k0 + lc) : z4;
        float4 bv1 = (nr1 < G3) ? *(const float4*)(W + (size_t)nr1 * Fdim + k0 + lc) : z4;
        __syncthreads();
        As[lc+0][lr] = av0.x; As[lc+1][lr] = av0.y; As[lc+2][lr] = av0.z; As[lc+3][lr] = av0.w;
        As[lc+0][lr+64] = av1.x; As[lc+1][lr+64] = av1.y; As[lc+2][lr+64] = av1.z; As[lc+3][lr+64] = av1.w;
        Bs[lc+0][lr] = bv0.x; Bs[lc+1][lr] = bv0.y; Bs[lc+2][lr] = bv0.z; Bs[lc+3][lr] = bv0.w;
        Bs[lc+0][lr+64] = bv1.x; Bs[lc+1][lr+64] = bv1.y; Bs[lc+2][lr+64] = bv1.z; Bs[lc+3][lr+64] = bv1.w;
        __syncthreads();
#pragma unroll
        for (int kk = 0; kk < 16; kk++) {
            float4 a0 = *(const float4*)&As[kk][ty * 8];
            float4 a1 = *(const float4*)&As[kk][ty * 8 + 4];
            ulonglong2 b01 = *(const ulonglong2*)&Bs[kk][tx * 8];
            ulonglong2 b23 = *(const ulonglong2*)&Bs[kk][tx * 8 + 4];
            unsigned long long bb[4] = {b01.x, b01.y, b23.x, b23.y};
            float a[8] = {a0.x, a0.y, a0.z, a0.w, a1.x, a1.y, a1.z, a1.w};
#pragma unroll
            for (int i = 0; i < 8; i++) {
                unsigned long long ad = pk(a[i], a[i]);
#pragma unroll
                for (int jj = 0; jj < 4; jj++) acc[i][jj] = ffma2(ad, bb[jj], acc[i][jj]);
            }
        }
    }
#pragma unroll
    for (int i = 0; i < 8; i++) {
        size_t m = m0 + (size_t)ty * 8 + i;
        float* Crow = g_XW + m * G3;
#pragma unroll
        for (int jj = 0; jj < 4; jj++) {
            int n = n0 + tx * 8 + jj * 2;
            if (n < G3) {
                float2 v = unpk(acc[i][jj]);
                float2 o;
                o.x = __fadd_rn(v.x, bias[n]);
                o.y = __fadd_rn(v.y, bias[n + 1]);
                *(float2*)(Crow + n) = o;
            }
        }
    }
}

// ---- recurrent pieces ----
__device__ __forceinline__ void stage_w(unsigned long long* wd, const float* Whh,
                                        int c, int tid) {
    for (int i = tid; i < 12 * Hdim; i += 256) {
        int lr = i / Hdim, k = i - lr * Hdim;
        int gr = (lr >> 2) * Hdim + 4 * c + (lr & 3);
        float w = Whh[(size_t)gr * Hdim + k];
        wd[lr * Hdim + k] = pk(w, w);
    }
}

// matvec on h2[k*64+b]: warp k8 owns k in [38*k8,38*k8+38), lane bp owns batches 2bp,2bp+1
__device__ __forceinline__ void gate_matvec(const unsigned long long* wd, float* ps,
                                            const float* h2, int tid) {
    const int k8 = tid >> 5, bp = tid & 31, b0 = 2 * bp;
    unsigned long long acc[12];
#pragma unroll
    for (int r = 0; r < 12; r++) acc[r] = 0ull;
    const int kbase = k8 * 38;
#pragma unroll
    for (int kk = 0; kk < 38; kk++) {
        float2 hv = __ldcg((const float2*)(h2 + (size_t)(kbase + kk) * 64 + b0));
        unsigned long long a = pk(hv.x, hv.y);
        const unsigned long long* wrow = wd + kbase + kk;
#pragma unroll
        for (int r = 0; r < 12; r++)
            acc[r] = ffma2(a, wrow[(size_t)r * Hdim], acc[r]);
    }
#pragma unroll
    for (int r = 0; r < 12; r++) {
        float2 v = unpk(acc[r]);
        *(float2*)&ps[(r * 8 + k8) * 64 + b0] = v;
    }
}

// pinned pairwise tree over the 8 warp partials
__device__ __forceinline__ float tree8(const float* p, int base, int b) {
    float s01 = __fadd_rn(p[(base + 0) * 64 + b], p[(base + 1) * 64 + b]);
    float s23 = __fadd_rn(p[(base + 2) * 64 + b], p[(base + 3) * 64 + b]);
    float s45 = __fadd_rn(p[(base + 4) * 64 + b], p[(base + 5) * 64 + b]);
    float s67 = __fadd_rn(p[(base + 6) * 64 + b], p[(base + 7) * 64 + b]);
    return __fadd_rn(__fadd_rn(s01, s23), __fadd_rn(s45, s67));
}

// pinned GRU update, reference-matching association: gate(ir + (gh + bhh))
__device__ __forceinline__ float gru_update(const float* ps, const float* gi_s,
                                            int ci, int b,
                                            float bR, float bZ, float bN, float hold) {
    float hr = __fadd_rn(tree8(ps, (0 + ci) * 8, b), bR);
    float hz = __fadd_rn(tree8(ps, (4 + ci) * 8, b), bZ);
    float hn = __fadd_rn(tree8(ps, (8 + ci) * 8, b), bN);
    float r = sigm(__fadd_rn(gi_s[(0 + ci) * 64 + b], hr));
    float z = sigm(__fadd_rn(gi_s[(4 + ci) * 64 + b], hz));
    float n = tanhf(__fadd_rn(gi_s[(8 + ci) * 64 + b], __fmul_rn(r, hn)));
    return __fadd_rn(__fmul_rn(__fsub_rn(1.0f, z), n), __fmul_rn(z, hold));
}

// smem (floats): wd 7296 | ps 6144 | gi_s 768 | (dec: lw 608 | red 256)
#define SME_F (7296 + 6144 + 768)
#define SMD_F (SME_F + 608 + 256)

__global__ void __launch_bounds__(256, 1)
enc_kernel(const float* __restrict__ Whh, const float* __restrict__ bhh) {
    extern __shared__ float sm[];
    unsigned long long* wd = (unsigned long long*)sm;
    float* ps   = sm + 7296;
    float* gi_s = ps + 6144;
    const int c = blockIdx.x, tid = threadIdx.x;
    const int ci = tid >> 6, b = tid & 63;

    stage_w(wd, Whh, c, tid);
    const float bR = bhh[4 * c + ci], bZ = bhh[Hdim + 4 * c + ci], bN = bhh[2 * Hdim + 4 * c + ci];
    unsigned ph = 1;
    gbar(&g_barE, ph * NCTA);

    int bb[3], nl[3];
#pragma unroll
    for (int q = 0; q < 3; q++) {
        int flat = q * 256 + tid;
        bb[q] = flat / 12; nl[q] = flat - bb[q] * 12;
    }

    for (int t = 0; t < Tlen; t++) {
        float gi[3];
#pragma unroll
        for (int q = 0; q < 3; q++) {
            int gr = (nl[q] >> 2) * Hdim + 4 * c + (nl[q] & 3);
            gi[q] = __ldg(&g_XW[((size_t)bb[q] * Tlen + t) * G3 + gr]);
        }
        const float* hb = g_h2[t & 1];
        gate_matvec(wd, ps, hb, tid);
#pragma unroll
        for (int q = 0; q < 3; q++) gi_s[nl[q] * 64 + bb[q]] = gi[q];
        __syncthreads();
        float hold = __ldcg(&hb[(size_t)(4 * c + ci) * 64 + b]);
        float hn = gru_update(ps, gi_s, ci, b, bR, bZ, bN, hold);
        __stcg(&g_h2[(t + 1) & 1][(size_t)(4 * c + ci) * 64 + b], hn);
        ph++;
        gbar(&g_barE, ph * NCTA);
    }
}

__global__ void __launch_bounds__(256, 1)
dec_kernel(const float* __restrict__ Whh, const float* __restrict__ bhh,
           const float* __restrict__ linW, const float* __restrict__ linb,
           float* __restrict__ out, int full) {
    extern __shared__ float sm[];
    unsigned long long* wd = (unsigned long long*)sm;
    float* ps   = sm + 7296;
    float* gi_s = ps + 6144;
    float* lw   = gi_s + 768;
    float* red  = lw + 608;
    __shared__ float rv[4];
    __shared__ int   ri[4];
    const int c = blockIdx.x, tid = threadIdx.x;
    const int ci = tid >> 6, b = tid & 63;

    stage_w(wd, Whh, c, tid);
    const float bR = bhh[4 * c + ci], bZ = bhh[Hdim + 4 * c + ci], bN = bhh[2 * Hdim + 4 * c + ci];
    float lb = 0.f;
    if (c < 64) {
        for (int i = tid; i < 2 * Hdim; i += 256)
            lw[i] = linW[(size_t)(2 * c + (i >= Hdim)) * Hdim + (i >= Hdim ? i - Hdim : i)];
        lb = linb[2 * c + ((tid >> 6) & 1)];
    }
    __syncthreads();   // FIX: staging must complete before first gate_matvec
    unsigned ph = 0;

    int bb[3], nl[3];
#pragma unroll
    for (int q = 0; q < 3; q++) {
        int flat = q * 256 + tid;
        bb[q] = flat / 12; nl[q] = flat - bb[q] * 12;
    }

    for (int l = 0; l < 127; l++) {
        const int rb = l & 1, wb = rb ^ 1;
        float gi[3];
#pragma unroll
        for (int q = 0; q < 3; q++) {
            int tok = __ldcg(&g_tok[bb[q]]);
            int gr = (nl[q] >> 2) * Hdim + 4 * c + (nl[q] & 3);
            gi[q] = __ldcg(&g_DW[(size_t)tok * G3 + gr]);
        }
        const float* hb = g_h2[rb];
        gate_matvec(wd, ps, hb, tid);
#pragma unroll
        for (int q = 0; q < 3; q++) gi_s[nl[q] * 64 + bb[q]] = gi[q];
        __syncthreads();
        float hold = __ldcg(&hb[(size_t)(4 * c + ci) * 64 + b]);
        float hn = gru_update(ps, gi_s, ci, b, bR, bZ, bN, hold);
        __stcg(&g_h2[wb][(size_t)(4 * c + ci) * 64 + b], hn);
        gbar(&g_barD, (++ph) * NCTA);

        // logits: CTAs 0..63 compute d = 2c+d2 for all batches; kh splits K
        float lacc = 0.f;
        if (c < 64) {
            const int b2 = tid & 63, d2 = (tid >> 6) & 1, kh = tid >> 7;
            const float* hsrc = g_h2[wb] + (size_t)kh * 152 * 64 + b2;
            const float* wsrc = lw + d2 * Hdim + kh * 152;
#pragma unroll 4
            for (int i = 0; i < 152; i++)
                lacc = __fmaf_rn(__ldcg(hsrc + (size_t)i * 64), wsrc[i], lacc);
        }
        red[tid] = lacc;
        __syncthreads();
        if (c < 64 && tid < 128) {
            const int b2 = tid & 63, d2 = (tid >> 6) & 1;
            float v = __fadd_rn(__fadd_rn(red[tid], red[tid + 128]), lb);
            out[((size_t)b2 * 127 + l) * Dvoc + 2 * c + d2] = v;
        }
        gbar(&g_barD, (++ph) * NCTA);

        // argmax per batch (CTA c = batch c), first-max tie-break
        if (c < 64 && tid < 128) {
            float v = __ldcg(&out[((size_t)c * 127 + l) * Dvoc + tid]);
            int   idx = tid;
#pragma unroll
            for (int o = 16; o > 0; o >>= 1) {
                float ov = __shfl_down_sync(0xffffffffu, v, o);
                int   oi = __shfl_down_sync(0xffffffffu, idx, o);
                if (ov > v || (ov == v && oi < idx)) { v = ov; idx = oi; }
            }
            if ((tid & 31) == 0) { rv[tid >> 5] = v; ri[tid >> 5] = idx; }
        }
        __syncthreads();
        if (c < 64 && tid == 0) {
            float bv = rv[0]; int bi = ri[0];
#pragma unroll
            for (int w = 1; w < 4; w++)
                if (rv[w] > bv || (rv[w] == bv && ri[w] < bi)) { bv = rv[w]; bi = ri[w]; }
            g_tok[c] = bi;
            if (full) out[ASR_OFF + c * 127 + l] = (float)bi;
        }
        gbar(&g_barD, (++ph) * NCTA);
    }
}

extern "C" void kernel_launch(void* const* d_in, const int* in_sizes, int n_in,
                              void* d_out, int out_size) {
    const float* x    = (const float*)d_in[0];
    const int*   tgt  = (const int*)  d_in[1];
    const float* emb  = (const float*)d_in[2];
    const float* eWih = (const float*)d_in[3];
    const float* eWhh = (const float*)d_in[4];
    const float* ebih = (const float*)d_in[5];
    const float* ebhh = (const float*)d_in[6];
    const float* dWih = (const float*)d_in[7];
    const float* dWhh = (const float*)d_in[8];
    const float* dbih = (const float*)d_in[9];
    const float* dbhh = (const float*)d_in[10];
    const float* linW = (const float*)d_in[11];
    const float* linb = (const float*)d_in[12];
    (void)in_sizes; (void)n_in;
    float* out = (float*)d_out;
    int full = (out_size >= FULL_N) ? 1 : 0;

    static int attr_done = 0;
    if (!attr_done) {
        cudaFuncSetAttribute(enc_kernel, cudaFuncAttributeMaxDynamicSharedMemorySize, SME_F * 4);
        cudaFuncSetAttribute(dec_kernel, cudaFuncAttributeMaxDynamicSharedMemorySize, SMD_F * 4);
        attr_done = 1;
    }

    init_kernel<<<64, 128>>>(tgt, out, full);
    dw_kernel<<<Dvoc, 928>>>(emb, dWih, dbih);
    gemm_xw<<<dim3(8, 512), 256>>>(x, eWih, ebih);
    enc_kernel<<<NCTA, 256, SME_F * 4>>>(eWhh, ebhh);
    dec_kernel<<<NCTA, 256, SMD_F * 4>>>(dWhh, dbhh, linW, linb, out, full);
}